// round 5
// baseline (speedup 1.0000x reference)
#include <cuda_runtime.h>
#include <cuda_bf16.h>
#include <cstdint>

// Problem constants
#define B_   64
#define L_   4096
#define KD_  128
#define H_   4
#define OUT_ 256

#define CHUNKS 8                 // L-chunks per batch (pass 1)
#define WARPS  4                 // warps per block in pass 1 (128 threads)
#define ROWS_PER_WARP (L_ / CHUNKS / WARPS)   // 128 (two 64-row bitmaps)
#define NBLK1 (B_ * CHUNKS)      // 512

#define OG_ 8                    // pass-2 output groups (32 outputs each)
#define BG_ 16                   // pass-2 batch groups (4 batches each)

// Deterministic scratch (no device allocation allowed)
__device__ float g_pacc[NBLK1][KD_ * H_];  // 512 x 512 f32 = 1 MB
__device__ float g_pZ[NBLK1][H_];

__device__ __forceinline__ float warp_sum32(float v) {
#pragma unroll
    for (int off = 16; off >= 1; off >>= 1)
        v += __shfl_xor_sync(0xffffffffu, v, off);
    return v;
}

// ---------------------------------------------------------------------------
// Pass 1. Per warp: 128 rows as two 64-bit mask bitmaps; live rows processed
// 8 per iteration. Scores for 8 rows x 4 heads = 32 scalars are reduced with
// ONE 5-level butterfly transpose-reduce (31 SHFL total): after it, lane l
// holds the full score of (row l>>2, head l&3). One __expf per lane per
// 8 rows. Weights broadcast through double-buffered shared memory.
// exp(-1e9)==0 in fp32 => skipping masked rows is exact; |score|<~4 => no
// max subtraction needed.
// ---------------------------------------------------------------------------
__global__ void __launch_bounds__(128, 4)
pool_pass1(const float* __restrict__ x,
           const int* __restrict__ mask,   // bool coerced to int32 by harness
           const float* __restrict__ q)
{
    const int blk  = blockIdx.x;
    const int b    = blk / CHUNKS;
    const int c    = blk % CHUNKS;
    const int w    = threadIdx.x >> 5;
    const int lane = threadIdx.x & 31;

    __shared__ float sP[WARPS][2][32];      // softmax-weight broadcast buffers
    __shared__ float sAcc[WARPS][KD_ * H_];
    __shared__ float sZ[WARPS][H_];

    // queries[h][lane*4 .. lane*4+3]
    float4 q4[H_];
#pragma unroll
    for (int h = 0; h < H_; h++)
        q4[h] = *reinterpret_cast<const float4*>(q + h * KD_ + lane * 4);

    float acc[4][H_];
#pragma unroll
    for (int j = 0; j < 4; j++)
#pragma unroll
        for (int h = 0; h < H_; h++) acc[j][h] = 0.0f;
    float zacc = 0.0f;                      // per-lane partial of Z[lane&3]

    const int l0 = c * (L_ / CHUNKS) + w * ROWS_PER_WARP;
    const float* xb = x + (size_t)b * L_ * KD_ + (size_t)l0 * KD_;
    const int* mb = mask + (size_t)b * L_ + l0;

    int pb = 0;
#pragma unroll 1
    for (int half = 0; half < 2; half++) {
        const unsigned m_lo = __ballot_sync(0xffffffffu, mb[half * 64 + lane] != 0);
        const unsigned m_hi = __ballot_sync(0xffffffffu, mb[half * 64 + 32 + lane] != 0);
        unsigned long long bits = ((unsigned long long)m_hi << 32) | (unsigned long long)m_lo;
        const float* xh = xb + (size_t)half * 64 * KD_;

        while (bits) {
            // ---- extract up to 8 live rows ----
            int r[8];
            unsigned liveIter = 0;
#pragma unroll
            for (int i = 0; i < 8; i++) {
                if (bits) {
                    r[i] = __ffsll((long long)bits) - 1;
                    bits &= bits - 1;
                    liveIter |= (1u << i);
                } else {
                    r[i] = r[0];            // padded slot, zero-weighted later
                }
            }

            // ---- 8 loads in flight ----
            float4 xv[8];
#pragma unroll
            for (int i = 0; i < 8; i++)
                xv[i] = *reinterpret_cast<const float4*>(xh + (size_t)r[i] * KD_ + lane * 4);

            // ---- per-lane dot partials: v[slot*4+h] ----
            float v[32];
#pragma unroll
            for (int i = 0; i < 8; i++)
#pragma unroll
                for (int h = 0; h < H_; h++)
                    v[i * 4 + h] = xv[i].x * q4[h].x + xv[i].y * q4[h].y
                                 + xv[i].z * q4[h].z + xv[i].w * q4[h].w;

            // ---- 32-value butterfly transpose-reduce (31 SHFL) ----
            // After step with offset `off`, surviving window's bit == lane bit.
            // End state: v[0] on lane l == full sum of value index l.
#pragma unroll
            for (int step = 0; step < 5; step++) {
                const int off  = 16 >> step;
                const int half_n = 16 >> step;   // surviving half size
                const bool up = (lane & off) != 0;
#pragma unroll
                for (int i = 0; i < 16; i++) {
                    if (i < half_n) {
                        const float send = up ? v[i] : v[i + half_n];
                        const float recv = __shfl_xor_sync(0xffffffffu, send, off);
                        v[i] = (up ? v[i + half_n] : v[i]) + recv;
                    }
                }
            }

            // ---- softmax weight: lane l = (row l>>2, head l&3) ----
            const int slot = lane >> 2;
            float e = __expf(v[0]);
            e = ((liveIter >> slot) & 1u) ? e : 0.0f;
            zacc += e;                       // Z[lane&3] partial

            sP[w][pb][lane] = e;
            __syncwarp();

            // ---- accumulate ----
#pragma unroll
            for (int i = 0; i < 8; i++) {
                const float4 pv = *reinterpret_cast<const float4*>(&sP[w][pb][i * 4]);
                acc[0][0] = fmaf(xv[i].x, pv.x, acc[0][0]);
                acc[0][1] = fmaf(xv[i].x, pv.y, acc[0][1]);
                acc[0][2] = fmaf(xv[i].x, pv.z, acc[0][2]);
                acc[0][3] = fmaf(xv[i].x, pv.w, acc[0][3]);
                acc[1][0] = fmaf(xv[i].y, pv.x, acc[1][0]);
                acc[1][1] = fmaf(xv[i].y, pv.y, acc[1][1]);
                acc[1][2] = fmaf(xv[i].y, pv.z, acc[1][2]);
                acc[1][3] = fmaf(xv[i].y, pv.w, acc[1][3]);
                acc[2][0] = fmaf(xv[i].z, pv.x, acc[2][0]);
                acc[2][1] = fmaf(xv[i].z, pv.y, acc[2][1]);
                acc[2][2] = fmaf(xv[i].z, pv.z, acc[2][2]);
                acc[2][3] = fmaf(xv[i].z, pv.w, acc[2][3]);
                acc[3][0] = fmaf(xv[i].w, pv.x, acc[3][0]);
                acc[3][1] = fmaf(xv[i].w, pv.y, acc[3][1]);
                acc[3][2] = fmaf(xv[i].w, pv.z, acc[3][2]);
                acc[3][3] = fmaf(xv[i].w, pv.w, acc[3][3]);
            }
            pb ^= 1;
        }
    }

    // Z[h] = sum of zacc over lanes with (lane&3)==h
    float zz = zacc;
#pragma unroll
    for (int off = 16; off >= 4; off >>= 1)
        zz += __shfl_xor_sync(0xffffffffu, zz, off);
    // lanes 0..3 now hold Z[0..3]

    // ---- block-level deterministic reduce ----
#pragma unroll
    for (int j = 0; j < 4; j++)
#pragma unroll
        for (int h = 0; h < H_; h++)
            sAcc[w][(lane * 4 + j) * H_ + h] = acc[j][h];   // idx = k*H + h
    if (lane < H_) sZ[w][lane] = zz;
    __syncthreads();

    for (int idx = threadIdx.x; idx < KD_ * H_; idx += 128) {
        float vv = 0.f;
#pragma unroll
        for (int ww = 0; ww < WARPS; ww++) vv += sAcc[ww][idx];
        g_pacc[blk][idx] = vv;
    }
    if (threadIdx.x < H_) {
        float vv = 0.f;
#pragma unroll
        for (int ww = 0; ww < WARPS; ww++) vv += sZ[ww][threadIdx.x];
        g_pZ[blk][threadIdx.x] = vv;
    }
}

// ---------------------------------------------------------------------------
// Pass 2: out = relu(pooled @ W^T + b + relu(emb[num])).
// Grid = OG_*BG_ = 128 blocks. Each warp caches the W rows of its 4 outputs
// in 64 registers and reuses them across 4 batches.
// ---------------------------------------------------------------------------
__global__ void __launch_bounds__(256, 4)
pool_pass2(const float* __restrict__ W,
           const float* __restrict__ bias,
           const float* __restrict__ emb,
           const int* __restrict__ num,
           float* __restrict__ out)
{
    const int og  = blockIdx.x / BG_;   // output group, 32 outputs
    const int bg  = blockIdx.x % BG_;   // batch group, 4 batches
    const int tid = threadIdx.x;
    const int wrp  = tid >> 5;
    const int lane = tid & 31;
    const int o0   = og * 32 + wrp * 4;

    __shared__ float pooled[KD_ * H_];
    __shared__ float Zs[H_];

    // Cache W for this warp's 4 outputs (lane-sliced): 16 float4 regs.
    float4 Wreg[4][4];
#pragma unroll
    for (int j = 0; j < 4; j++)
#pragma unroll
        for (int qi = 0; qi < 4; qi++)
            Wreg[j][qi] = *reinterpret_cast<const float4*>(
                W + (size_t)(o0 + j) * (KD_ * H_) + qi * 128 + lane * 4);

    float bj[4];
#pragma unroll
    for (int j = 0; j < 4; j++) bj[j] = bias[o0 + j];

#pragma unroll 1
    for (int bi = 0; bi < 4; bi++) {
        const int b = bg * 4 + bi;
        __syncthreads();   // protect smem reuse across batches

        if (tid < H_) {
            float vv = 0.f;
#pragma unroll
            for (int c = 0; c < CHUNKS; c++) vv += g_pZ[b * CHUNKS + c][tid];
            Zs[tid] = vv;
        }
        for (int idx = tid; idx < KD_ * H_; idx += 256) {
            float vv = 0.f;
#pragma unroll
            for (int c = 0; c < CHUNKS; c++) vv += g_pacc[b * CHUNKS + c][idx];
            pooled[idx] = vv;
        }
        __syncthreads();
        for (int idx = tid; idx < KD_ * H_; idx += 256)
            pooled[idx] = pooled[idx] / Zs[idx & (H_ - 1)];
        __syncthreads();

        float4 pv[4];
#pragma unroll
        for (int qi = 0; qi < 4; qi++)
            pv[qi] = *reinterpret_cast<const float4*>(&pooled[qi * 128 + lane * 4]);

        float a[4];
#pragma unroll
        for (int j = 0; j < 4; j++) {
            float s = 0.f;
#pragma unroll
            for (int qi = 0; qi < 4; qi++)
                s = fmaf(Wreg[j][qi].x, pv[qi].x,
                    fmaf(Wreg[j][qi].y, pv[qi].y,
                    fmaf(Wreg[j][qi].z, pv[qi].z,
                    fmaf(Wreg[j][qi].w, pv[qi].w, s))));
            a[j] = warp_sum32(s);
        }

        if (lane == 0) {
            const int nb = num[b];
#pragma unroll
            for (int j = 0; j < 4; j++) {
                const int o = o0 + j;
                float vv = a[j] + bj[j] + fmaxf(emb[(size_t)nb * OUT_ + o], 0.f);
                out[(size_t)b * OUT_ + o] = fmaxf(vv, 0.f);
            }
        }
    }
}

// ---------------------------------------------------------------------------
// Launch.  Inputs (metadata order): x, mask, num, queries, W, b, emb
// ---------------------------------------------------------------------------
extern "C" void kernel_launch(void* const* d_in, const int* in_sizes, int n_in,
                              void* d_out, int out_size)
{
    const float* x    = (const float*)d_in[0];
    const int*   mask = (const int*)d_in[1];     // bool -> int32 on upload
    const int*   num  = (const int*)d_in[2];
    const float* q    = (const float*)d_in[3];
    const float* W    = (const float*)d_in[4];
    const float* bias = (const float*)d_in[5];
    const float* emb  = (const float*)d_in[6];
    float*       out  = (float*)d_out;

    pool_pass1<<<NBLK1, 128>>>(x, mask, q);
    pool_pass2<<<OG_ * BG_, 256>>>(W, bias, emb, num, out);
}

// round 7
// speedup vs baseline: 1.2297x; 1.2297x over previous
#include <cuda_runtime.h>
#include <cuda_bf16.h>
#include <cstdint>

// Problem constants
#define B_   64
#define L_   4096
#define KD_  128
#define H_   4
#define OUT_ 256

#define CHUNKS 16                // L-chunks per batch (pass 1)
#define WARPS  4                 // warps per block in pass 1 (128 threads)
#define ROWS_PER_WARP (L_ / CHUNKS / WARPS)   // 64 -> one 64-bit bitmap/warp
#define NBLK1 (B_ * CHUNKS)      // 1024

// Deterministic scratch (no device allocation allowed)
__device__ float g_pacc[NBLK1][KD_ * H_];   // 1024 x 512 f32 = 2 MB
__device__ float g_pZ[NBLK1][H_];
__device__ float g_pooled[B_][KD_ * H_];    // normalized pooled vectors

__device__ __forceinline__ float warp_sum32(float v) {
#pragma unroll
    for (int off = 16; off >= 1; off >>= 1)
        v += __shfl_xor_sync(0xffffffffu, v, off);
    return v;
}

// Pop up to 4 set bits; returns liveness mask (bit i = slot i valid).
__device__ __forceinline__ unsigned extract4(unsigned long long& bits, int r[4]) {
    unsigned live = 0;
    r[0] = 0;
#pragma unroll
    for (int i = 0; i < 4; i++) {
        if (bits) {
            r[i] = __ffsll((long long)bits) - 1;
            bits &= bits - 1;
            live |= 1u << i;
        } else {
            r[i] = r[0];               // padded duplicate, zero-weighted later
        }
    }
    return live;
}

// ---------------------------------------------------------------------------
// Pass 1. Warp owns 64 rows (one 64-bit mask bitmap). Live rows processed
// 4 per iteration with software prefetch of the next 4 row loads.
// Scores: 4 rows x 4 heads = 16 values. 4-level butterfly (offsets 8,4,2,1)
// transpose-reduces them WITHIN each 16-lane half; the final offset-16
// exchange adds the two half-sums, completing the 32-lane dot product
// (this was the R6 bug: that exchange was missing). After it every lane l
// holds the full score of value (l & 15) = (row (l&15)>>2, head l&3).
// One __expf per lane per 4 rows; weights broadcast via smem.
// exp(-1e9)==0 in fp32 => skipping masked rows is exact; |score|<~4 => no
// max subtraction needed.
// ---------------------------------------------------------------------------
__global__ void __launch_bounds__(128, 5)
pool_pass1(const float* __restrict__ x,
           const int* __restrict__ mask,   // bool coerced to int32 by harness
           const float* __restrict__ q)
{
    const int blk  = blockIdx.x;
    const int b    = blk / CHUNKS;
    const int c    = blk % CHUNKS;
    const int w    = threadIdx.x >> 5;
    const int lane = threadIdx.x & 31;

    __shared__ float sP[WARPS][2][16];      // softmax-weight broadcast buffers
    __shared__ float sAcc[WARPS][KD_ * H_];
    __shared__ float sZ[WARPS][H_];

    float4 q4[H_];
#pragma unroll
    for (int h = 0; h < H_; h++)
        q4[h] = *reinterpret_cast<const float4*>(q + h * KD_ + lane * 4);

    float acc[4][H_];
#pragma unroll
    for (int j = 0; j < 4; j++)
#pragma unroll
        for (int h = 0; h < H_; h++) acc[j][h] = 0.0f;
    float zacc = 0.0f;

    const int l0 = c * (L_ / CHUNKS) + w * ROWS_PER_WARP;
    const float* xb = x + (size_t)b * L_ * KD_ + (size_t)l0 * KD_;
    const int* mb = mask + (size_t)b * L_ + l0;

    const unsigned m_lo = __ballot_sync(0xffffffffu, mb[lane] != 0);
    const unsigned m_hi = __ballot_sync(0xffffffffu, mb[32 + lane] != 0);
    unsigned long long bits = ((unsigned long long)m_hi << 32) | (unsigned long long)m_lo;

    int r[4];
    float4 xv[4];
    unsigned live = extract4(bits, r);
    if (live) {
#pragma unroll
        for (int i = 0; i < 4; i++)
            xv[i] = *reinterpret_cast<const float4*>(xb + (size_t)r[i] * KD_ + lane * 4);
    }

    int pb = 0;
    while (live) {
        // ---- prefetch next 4 rows (loads in flight during compute) ----
        int rn[4];
        float4 xvn[4];
        const unsigned liveN = extract4(bits, rn);
        if (liveN) {
#pragma unroll
            for (int i = 0; i < 4; i++)
                xvn[i] = *reinterpret_cast<const float4*>(xb + (size_t)rn[i] * KD_ + lane * 4);
        }

        // ---- per-lane dot partials: v[slot*4+h] ----
        float v[16];
#pragma unroll
        for (int i = 0; i < 4; i++)
#pragma unroll
            for (int h = 0; h < H_; h++)
                v[i * 4 + h] = xv[i].x * q4[h].x + xv[i].y * q4[h].y
                             + xv[i].z * q4[h].z + xv[i].w * q4[h].w;

        // ---- 16-value butterfly transpose-reduce within 16-lane halves ----
#pragma unroll
        for (int step = 0; step < 4; step++) {
            const int off = 8 >> step;
            const bool up = (lane & off) != 0;
#pragma unroll
            for (int i = 0; i < 8; i++) {
                if (i < (8 >> step)) {
                    const float send = up ? v[i] : v[i + (8 >> step)];
                    const float recv = __shfl_xor_sync(0xffffffffu, send, off);
                    v[i] = (up ? v[i + (8 >> step)] : v[i]) + recv;
                }
            }
        }
        // Combine the two 16-lane half-sums -> full 32-lane dot product.
        v[0] += __shfl_xor_sync(0xffffffffu, v[0], 16);

        // ---- softmax weight: every lane l holds value (l & 15) ----
        float e = __expf(v[0]);
        const unsigned s = (lane & 15) >> 2;
        e = ((live >> s) & 1u) ? e : 0.0f;
        if (lane < 16) sP[w][pb][lane] = e; else e = 0.0f;
        zacc += e;                         // Z[lane&3] partial (lanes<16 only)
        __syncwarp();

        // ---- accumulate 4 rows ----
#pragma unroll
        for (int i = 0; i < 4; i++) {
            const float4 pv = *reinterpret_cast<const float4*>(&sP[w][pb][i * 4]);
            acc[0][0] = fmaf(xv[i].x, pv.x, acc[0][0]);
            acc[0][1] = fmaf(xv[i].x, pv.y, acc[0][1]);
            acc[0][2] = fmaf(xv[i].x, pv.z, acc[0][2]);
            acc[0][3] = fmaf(xv[i].x, pv.w, acc[0][3]);
            acc[1][0] = fmaf(xv[i].y, pv.x, acc[1][0]);
            acc[1][1] = fmaf(xv[i].y, pv.y, acc[1][1]);
            acc[1][2] = fmaf(xv[i].y, pv.z, acc[1][2]);
            acc[1][3] = fmaf(xv[i].y, pv.w, acc[1][3]);
            acc[2][0] = fmaf(xv[i].z, pv.x, acc[2][0]);
            acc[2][1] = fmaf(xv[i].z, pv.y, acc[2][1]);
            acc[2][2] = fmaf(xv[i].z, pv.z, acc[2][2]);
            acc[2][3] = fmaf(xv[i].z, pv.w, acc[2][3]);
            acc[3][0] = fmaf(xv[i].w, pv.x, acc[3][0]);
            acc[3][1] = fmaf(xv[i].w, pv.y, acc[3][1]);
            acc[3][2] = fmaf(xv[i].w, pv.z, acc[3][2]);
            acc[3][3] = fmaf(xv[i].w, pv.w, acc[3][3]);
        }
        pb ^= 1;

        // rotate prefetch buffers
        live = liveN;
#pragma unroll
        for (int i = 0; i < 4; i++) xv[i] = xvn[i];
    }

    // Z[h] = sum of zacc over lanes with (lane&3)==h -> lanes 0..3
    float zz = zacc;
#pragma unroll
    for (int off = 16; off >= 4; off >>= 1)
        zz += __shfl_xor_sync(0xffffffffu, zz, off);

    // ---- block-level deterministic reduce ----
#pragma unroll
    for (int j = 0; j < 4; j++)
#pragma unroll
        for (int h = 0; h < H_; h++)
            sAcc[w][(lane * 4 + j) * H_ + h] = acc[j][h];   // idx = k*H + h
    if (lane < H_) sZ[w][lane] = zz;
    __syncthreads();

    for (int idx = threadIdx.x; idx < KD_ * H_; idx += 128) {
        float vv = 0.f;
#pragma unroll
        for (int ww = 0; ww < WARPS; ww++) vv += sAcc[ww][idx];
        g_pacc[blk][idx] = vv;
    }
    if (threadIdx.x < H_) {
        float vv = 0.f;
#pragma unroll
        for (int ww = 0; ww < WARPS; ww++) vv += sZ[ww][threadIdx.x];
        g_pZ[blk][threadIdx.x] = vv;
    }
}

// ---------------------------------------------------------------------------
// Pass 2a: combine chunk partials + normalize -> g_pooled[b][*].
// 64 blocks x 512 threads: one thread per pooled element, 16 independent loads.
// ---------------------------------------------------------------------------
__global__ void __launch_bounds__(512, 2)
pool_combine()
{
    const int b   = blockIdx.x;
    const int tid = threadIdx.x;
    __shared__ float Zs[H_];

    if (tid < H_) {
        float vv = 0.f;
#pragma unroll
        for (int c = 0; c < CHUNKS; c++) vv += g_pZ[b * CHUNKS + c][tid];
        Zs[tid] = vv;
    }
    float vv = 0.f;
#pragma unroll
    for (int c = 0; c < CHUNKS; c++) vv += g_pacc[b * CHUNKS + c][tid];
    __syncthreads();
    g_pooled[b][tid] = vv / Zs[tid & (H_ - 1)];
}

// ---------------------------------------------------------------------------
// Pass 2b: out = relu(pooled @ W^T + b + relu(emb[num])).
// Grid = B * 8 blocks (batch x 32-output group); warp computes 4 outputs
// from 16 independent W float4 loads against smem-cached pooled.
// ---------------------------------------------------------------------------
__global__ void __launch_bounds__(256, 4)
pool_gemv(const float* __restrict__ W,
          const float* __restrict__ bias,
          const float* __restrict__ emb,
          const int* __restrict__ num,
          float* __restrict__ out)
{
    const int b    = blockIdx.x >> 3;
    const int og   = blockIdx.x & 7;
    const int tid  = threadIdx.x;
    const int wrp  = tid >> 5;
    const int lane = tid & 31;
    const int o0   = og * 32 + wrp * 4;

    __shared__ float pooled[KD_ * H_];
    for (int idx = tid; idx < (KD_ * H_) / 4; idx += 256)
        reinterpret_cast<float4*>(pooled)[idx] =
            reinterpret_cast<const float4*>(g_pooled[b])[idx];
    __syncthreads();

    float4 pv[4];
#pragma unroll
    for (int qi = 0; qi < 4; qi++)
        pv[qi] = *reinterpret_cast<const float4*>(&pooled[qi * 128 + lane * 4]);

    float a[4];
#pragma unroll
    for (int j = 0; j < 4; j++) {
        const float* Wr = W + (size_t)(o0 + j) * (KD_ * H_);
        float ssum = 0.f;
#pragma unroll
        for (int qi = 0; qi < 4; qi++) {
            const float4 wv = *reinterpret_cast<const float4*>(Wr + qi * 128 + lane * 4);
            ssum = fmaf(wv.x, pv[qi].x, fmaf(wv.y, pv[qi].y,
                   fmaf(wv.z, pv[qi].z, fmaf(wv.w, pv[qi].w, ssum))));
        }
        a[j] = warp_sum32(ssum);
    }

    if (lane == 0) {
        const int nb = num[b];
#pragma unroll
        for (int j = 0; j < 4; j++) {
            const int o = o0 + j;
            float vv = a[j] + bias[o] + fmaxf(emb[(size_t)nb * OUT_ + o], 0.f);
            out[(size_t)b * OUT_ + o] = fmaxf(vv, 0.f);
        }
    }
}

// ---------------------------------------------------------------------------
// Launch.  Inputs (metadata order): x, mask, num, queries, W, b, emb
// ---------------------------------------------------------------------------
extern "C" void kernel_launch(void* const* d_in, const int* in_sizes, int n_in,
                              void* d_out, int out_size)
{
    const float* x    = (const float*)d_in[0];
    const int*   mask = (const int*)d_in[1];     // bool -> int32 on upload
    const int*   num  = (const int*)d_in[2];
    const float* q    = (const float*)d_in[3];
    const float* W    = (const float*)d_in[4];
    const float* bias = (const float*)d_in[5];
    const float* emb  = (const float*)d_in[6];
    float*       out  = (float*)d_out;

    pool_pass1<<<NBLK1, 128>>>(x, mask, q);
    pool_combine<<<B_, 512>>>();
    pool_gemv<<<B_ * 8, 256>>>(W, bias, emb, num, out);
}